// round 1
// baseline (speedup 1.0000x reference)
#include <cuda_runtime.h>

// Problem constants
#define BB      16
#define YSZ     256
#define XSZ     256
#define HD      128
#define TILE_P  128
#define PITCH   132            // 128 + 4 pad (multiple of 4 for float4 alignment)
#define NBLOCKS (BB * YSZ * (XSZ / TILE_P))   // 8192

// Per-block partial sums (deterministic final reduction, no atomics)
__device__ float g_partial[NBLOCKS];

__device__ __forceinline__ float fast_tanh(float x) {
    float y;
    asm("tanh.approx.f32 %0, %1;" : "=f"(y) : "f"(x));
    return y;
}

// SMEM layout (floats):
//   As   : HD * PITCH        activations [feature][pixel]
//   W2s  : HD * PITCH        W2 [j][k]
//   W3s  : HD * PITCH        W3 [j][k]
//   base : HD                x*W1[0] + t*W1[2] + b1
//   w1y  : HD                W1[1]
//   w4s  : HD
//   b2s  : HD
//   b3s  : HD
#define SMEM_FLOATS (3 * HD * PITCH + 5 * HD)
#define SMEM_BYTES  (SMEM_FLOATS * 4)

__global__ void __launch_bounds__(256, 1)
mlp_loss_kernel(const float* __restrict__ images,
                const float* __restrict__ W1, const float* __restrict__ b1,
                const float* __restrict__ W2, const float* __restrict__ b2,
                const float* __restrict__ W3, const float* __restrict__ b3,
                const float* __restrict__ W4, const float* __restrict__ b4,
                const int*   nptr)
{
    extern __shared__ float sm[];
    float* As   = sm;
    float* W2s  = sm + HD * PITCH;
    float* W3s  = sm + 2 * HD * PITCH;
    float* base = sm + 3 * HD * PITCH;
    float* w1y  = base + HD;
    float* w4s  = base + 2 * HD;
    float* b2s  = base + 3 * HD;
    float* b3s  = base + 4 * HD;

    const int tid = threadIdx.x;
    const int blk = blockIdx.x;
    const int b   = blk >> 9;          // / (YSZ * 2)
    const int rem = blk & 511;
    const int r   = rem >> 1;          // image row (x-coordinate index)
    const int c0  = (rem & 1) << 7;    // column tile start

    const int nv  = (nptr != nullptr) ? nptr[0] : 0;
    const float tv = (float)(b + nv * BB);
    const float STEP = 256.0f / 255.0f;
    const float xr = -128.0f + (float)r * STEP;

    // ---- Stage weights into shared ----
    #pragma unroll 4
    for (int i = tid; i < HD * HD; i += 256) {
        int j = i >> 7, k = i & 127;
        W2s[j * PITCH + k] = W2[i];
        W3s[j * PITCH + k] = W3[i];
    }
    if (tid < HD) {
        base[tid] = xr * W1[tid] + tv * W1[2 * HD + tid] + b1[tid];
        w1y[tid]  = W1[HD + tid];
        w4s[tid]  = W4[tid];
        b2s[tid]  = b2[tid];
        b3s[tid]  = b3[tid];
    }
    __syncthreads();

    // ---- Layer 1 (separable): As[j][pix] = tanh(base[j] + y_c * W1[1][j]) ----
    #pragma unroll 4
    for (int idx = tid; idx < HD * TILE_P; idx += 256) {
        int j   = idx >> 7;
        int pix = idx & 127;
        float yc = -128.0f + (float)(c0 + pix) * STEP;
        As[j * PITCH + pix] = fast_tanh(base[j] + yc * w1y[j]);
    }
    __syncthreads();

    // ---- Layers 2 and 3: 128x128 GEMM + tanh, in-place ping on As ----
    const int tx = tid & 15;   // k micro-tile: k = tx + 16*v
    const int ty = tid >> 4;   // pixel micro-tile: pix = ty*8 + u
    const int p0 = ty * 8;

    #pragma unroll 1
    for (int layer = 0; layer < 2; ++layer) {
        const float* Ws = layer ? W3s : W2s;
        const float* bs = layer ? b3s : b2s;

        float acc[64];
        #pragma unroll
        for (int i = 0; i < 64; ++i) acc[i] = 0.0f;

        #pragma unroll 4
        for (int j = 0; j < HD; ++j) {
            float4 a0 = *(const float4*)(As + j * PITCH + p0);
            float4 a1 = *(const float4*)(As + j * PITCH + p0 + 4);
            float aa[8] = {a0.x, a0.y, a0.z, a0.w, a1.x, a1.y, a1.z, a1.w};
            float ww[8];
            #pragma unroll
            for (int v = 0; v < 8; ++v) ww[v] = Ws[j * PITCH + tx + 16 * v];
            #pragma unroll
            for (int u = 0; u < 8; ++u)
                #pragma unroll
                for (int v = 0; v < 8; ++v)
                    acc[u * 8 + v] += aa[u] * ww[v];
        }
        __syncthreads();   // all reads of As done

        #pragma unroll
        for (int v = 0; v < 8; ++v) {
            int k = tx + 16 * v;
            float bk = bs[k];
            #pragma unroll
            for (int u = 0; u < 8; ++u)
                As[k * PITCH + p0 + u] = fast_tanh(acc[u * 8 + v] + bk);
        }
        __syncthreads();
    }

    // ---- Layer 4 + squared error (threads 0..127, one pixel each) ----
    float lsum = 0.0f;
    if (tid < TILE_P) {
        float acc = b4[0];
        #pragma unroll 8
        for (int j = 0; j < HD; ++j)
            acc += As[j * PITCH + tid] * w4s[j];
        float img = images[((size_t)b * YSZ + r) * XSZ + c0 + tid];
        float e = img - acc;
        lsum = e * e;
    }
    __syncthreads();   // done reading As; reuse it for reduction

    sm[tid] = lsum;    // threads >= 128 contribute 0
    __syncthreads();
    #pragma unroll
    for (int s = 128; s > 0; s >>= 1) {
        if (tid < s) sm[tid] += sm[tid + s];
        __syncthreads();
    }
    if (tid == 0) g_partial[blk] = sm[0];
}

__global__ void reduce_kernel(float* __restrict__ out)
{
    __shared__ float s[256];
    float a = 0.0f;
    for (int i = threadIdx.x; i < NBLOCKS; i += 256)
        a += g_partial[i];
    s[threadIdx.x] = a;
    __syncthreads();
    #pragma unroll
    for (int st = 128; st > 0; st >>= 1) {
        if (threadIdx.x < st) s[threadIdx.x] += s[threadIdx.x + st];
        __syncthreads();
    }
    if (threadIdx.x == 0)
        out[0] = s[0] * (1.0f / (float)(BB * YSZ * XSZ));
}

extern "C" void kernel_launch(void* const* d_in, const int* in_sizes, int n_in,
                              void* d_out, int out_size)
{
    const float* images = (const float*)d_in[0];
    const float* W1     = (const float*)d_in[1];
    const float* b1     = (const float*)d_in[2];
    const float* W2     = (const float*)d_in[3];
    const float* b2     = (const float*)d_in[4];
    const float* W3     = (const float*)d_in[5];
    const float* b3     = (const float*)d_in[6];
    const float* W4     = (const float*)d_in[7];
    const float* b4     = (const float*)d_in[8];
    const int*   nptr   = (n_in > 10) ? (const int*)d_in[10] : nullptr;

    cudaFuncSetAttribute(mlp_loss_kernel,
                         cudaFuncAttributeMaxDynamicSharedMemorySize, SMEM_BYTES);

    mlp_loss_kernel<<<NBLOCKS, 256, SMEM_BYTES>>>(images, W1, b1, W2, b2,
                                                  W3, b3, W4, b4, nptr);
    reduce_kernel<<<1, 256>>>((float*)d_out);
}

// round 3
// speedup vs baseline: 6.9566x; 6.9566x over previous
#include <cuda_runtime.h>
#include <cuda_bf16.h>
#include <cstdint>

// ---------------- problem constants ----------------
#define BB        16
#define HD        128
#define NBLK      2048
#define TILES_PER 4                  // 2048*4 = 8192 tiles of 128 pixels
#define STEPC     (256.0f/255.0f)

// ---------------- smem layout (bytes) ----------------
// acts: bf16 [128 pixels][pitch 136]  (272 B rows, 16B-aligned, conflict-free ldmatrix)
#define PFB       272               // pitch in bytes
#define SM_ACT    0
#define SM_W2     34816
#define SM_W3     69632
#define SM_B2     104448            // float[128]
#define SM_B3     104960
#define SM_W4     105472
#define SM_L1P    105984            // float2[128] {base, w1y}
#define SM_PART   107008            // float[4][128]
#define SM_RED    109056            // float[256]
#define SM_TOTAL  110592

__device__ float g_partial[NBLK];

__device__ __forceinline__ uint32_t smem_u32(const void* p) {
    uint32_t a;
    asm("{ .reg .u64 t; cvta.to.shared.u64 t, %1; cvt.u32.u64 %0, t; }"
        : "=r"(a) : "l"(p));
    return a;
}
__device__ __forceinline__ float tanh_fast(float x) {
    float y; asm("tanh.approx.f32 %0, %1;" : "=f"(y) : "f"(x)); return y;
}

#define LDSM4(r, addr) \
    asm volatile("ldmatrix.sync.aligned.m8n8.x4.shared.b16 {%0,%1,%2,%3}, [%4];" \
        : "=r"((r)[0]), "=r"((r)[1]), "=r"((r)[2]), "=r"((r)[3]) : "r"(addr))

#define MMA16816(c, a, b0, b1) \
    asm volatile("mma.sync.aligned.m16n8k16.row.col.f32.bf16.bf16.f32 " \
        "{%0,%1,%2,%3}, {%4,%5,%6,%7}, {%8,%9}, {%0,%1,%2,%3};" \
        : "+f"((c)[0]), "+f"((c)[1]), "+f"((c)[2]), "+f"((c)[3]) \
        : "r"((a)[0]), "r"((a)[1]), "r"((a)[2]), "r"((a)[3]), "r"(b0), "r"(b1))

// pack: lo -> bits[15:0], hi -> bits[31:16]
#define CVT_BF16X2(res, lo, hi) \
    asm("cvt.rn.bf16x2.f32 %0, %1, %2;" : "=r"(res) : "f"(hi), "f"(lo))

// GEMM: acc[mt][ns][4] += acts[mh-half] @ W^T[nq-quarter], K=128
__device__ __forceinline__ void gemm128(uint32_t sb, uint32_t w_off,
                                        int mh, int nq, int lane, float* acc)
{
    const uint32_t a_base = sb + SM_ACT
        + (uint32_t)((mh * 64 + (lane & 15)) * PFB + (lane >> 4) * 16);
    const uint32_t b_base = sb + w_off
        + (uint32_t)((nq * 32 + ((lane >> 4) << 3) + (lane & 7)) * PFB
                     + ((lane >> 3) & 1) * 16);
    #pragma unroll
    for (int kk = 0; kk < 8; ++kk) {
        const uint32_t ko = (uint32_t)kk * 32;   // 16 k-elems * 2B
        uint32_t b0r[4], b1r[4];
        LDSM4(b0r, b_base + ko);                 // n-subs 0,1 of this quarter
        LDSM4(b1r, b_base + 16 * PFB + ko);      // n-subs 2,3
        #pragma unroll
        for (int mt = 0; mt < 4; ++mt) {
            uint32_t ar[4];
            LDSM4(ar, a_base + (uint32_t)(mt * 16) * PFB + ko);
            MMA16816(&acc[(mt * 4 + 0) * 4], ar, b0r[0], b0r[1]);
            MMA16816(&acc[(mt * 4 + 1) * 4], ar, b0r[2], b0r[3]);
            MMA16816(&acc[(mt * 4 + 2) * 4], ar, b1r[0], b1r[1]);
            MMA16816(&acc[(mt * 4 + 3) * 4], ar, b1r[2], b1r[3]);
        }
    }
}

__global__ void __launch_bounds__(256, 2)
mlp_mma_kernel(const float* __restrict__ images,
               const float* __restrict__ W1, const float* __restrict__ b1,
               const float* __restrict__ W2, const float* __restrict__ b2,
               const float* __restrict__ W3, const float* __restrict__ b3,
               const float* __restrict__ W4, const float* __restrict__ b4,
               const int*   nptr)
{
    extern __shared__ char smem[];
    const uint32_t sb = smem_u32(smem);
    const int tid  = threadIdx.x;
    const int lane = tid & 31;
    const int wid  = tid >> 5;
    const int mh   = wid >> 2;          // pixel half (0/1): rows [mh*64, +64)
    const int nq   = wid & 3;           // feature quarter: cols [nq*32, +32)
    const int gid  = lane >> 2;
    const int tig  = lane & 3;

    // ---- stage weights (transposed, bf16) ----
    #pragma unroll 4
    for (int i = tid; i < HD * HD; i += 256) {
        int k = i >> 7, n = i & 127;
        uint32_t off = (uint32_t)(n * PFB + k * 2);
        *(__nv_bfloat16*)(smem + SM_W2 + off) = __float2bfloat16(W2[i]);
        *(__nv_bfloat16*)(smem + SM_W3 + off) = __float2bfloat16(W3[i]);
    }
    if (tid < HD) {
        ((float*)(smem + SM_B2))[tid] = b2[tid];
        ((float*)(smem + SM_B3))[tid] = b3[tid];
        ((float*)(smem + SM_W4))[tid] = W4[tid];
    }

    const int   nv  = (nptr != nullptr) ? nptr[0] : 0;
    const float b4v = b4[0];
    const float* b2s = (const float*)(smem + SM_B2);
    const float* b3s = (const float*)(smem + SM_B3);
    const float* w4s = (const float*)(smem + SM_W4);
    float* part = (float*)(smem + SM_PART);

    float lacc = 0.0f;

    for (int it = 0; it < TILES_PER; ++it) {
        const int tile = blockIdx.x * TILES_PER + it;
        const int b  = tile >> 9;
        const int r  = (tile >> 1) & 255;
        const int c0 = (tile & 1) << 7;
        const float tv = (float)(b + nv * BB);
        const float xr = -128.0f + (float)r * STEPC;

        __syncthreads();   // part/acts of previous tile fully consumed
        if (tid < HD) {
            float2 v;
            v.x = fmaf(xr, W1[tid], fmaf(tv, W1[2 * HD + tid], b1[tid]));
            v.y = W1[HD + tid];
            ((float2*)(smem + SM_L1P))[tid] = v;
        }
        __syncthreads();

        // ---- layer 1 -> acts (bf16) ----
        {
            const int p  = tid & 127;
            const int hf = tid >> 7;
            const float yc = -128.0f + (float)(c0 + p) * STEPC;
            const float2* l1p = (const float2*)(smem + SM_L1P);
            char* arow = smem + SM_ACT + p * PFB + hf * 128;
            #pragma unroll
            for (int j = 0; j < 32; ++j) {
                float2 q0 = l1p[hf * 64 + 2 * j];
                float2 q1 = l1p[hf * 64 + 2 * j + 1];
                float v0 = tanh_fast(fmaf(yc, q0.y, q0.x));
                float v1 = tanh_fast(fmaf(yc, q1.y, q1.x));
                uint32_t pk; CVT_BF16X2(pk, v0, v1);
                *(uint32_t*)(arow + 4 * j) = pk;
            }
        }
        __syncthreads();

        // ---- layer 2: mma + tanh epilogue (in-place on acts) ----
        {
            float acc[64];
            #pragma unroll
            for (int i = 0; i < 64; ++i) acc[i] = 0.0f;
            gemm128(sb, SM_W2, mh, nq, lane, acc);
            __syncthreads();   // all reads of acts complete
            #pragma unroll
            for (int mt = 0; mt < 4; ++mt) {
                const int row = mh * 64 + mt * 16 + gid;
                #pragma unroll
                for (int ns = 0; ns < 4; ++ns) {
                    const float* c = &acc[(mt * 4 + ns) * 4];
                    const int col = nq * 32 + ns * 8 + 2 * tig;
                    float v0 = tanh_fast(c[0] + b2s[col]);
                    float v1 = tanh_fast(c[1] + b2s[col + 1]);
                    float v2 = tanh_fast(c[2] + b2s[col]);
                    float v3 = tanh_fast(c[3] + b2s[col + 1]);
                    uint32_t p01, p23;
                    CVT_BF16X2(p01, v0, v1);
                    CVT_BF16X2(p23, v2, v3);
                    *(uint32_t*)(smem + SM_ACT + row * PFB + col * 2) = p01;
                    *(uint32_t*)(smem + SM_ACT + (row + 8) * PFB + col * 2) = p23;
                }
            }
        }
        __syncthreads();

        // ---- layer 3: mma + fused tanh + W4 dot ----
        {
            float acc[64];
            #pragma unroll
            for (int i = 0; i < 64; ++i) acc[i] = 0.0f;
            gemm128(sb, SM_W3, mh, nq, lane, acc);
            #pragma unroll
            for (int mt = 0; mt < 4; ++mt) {
                float p0 = 0.0f, p1 = 0.0f;
                #pragma unroll
                for (int ns = 0; ns < 4; ++ns) {
                    const float* c = &acc[(mt * 4 + ns) * 4];
                    const int col = nq * 32 + ns * 8 + 2 * tig;
                    float w0 = w4s[col], w1 = w4s[col + 1];
                    float bb0 = b3s[col], bb1 = b3s[col + 1];
                    p0 = fmaf(tanh_fast(c[0] + bb0), w0, p0);
                    p0 = fmaf(tanh_fast(c[1] + bb1), w1, p0);
                    p1 = fmaf(tanh_fast(c[2] + bb0), w0, p1);
                    p1 = fmaf(tanh_fast(c[3] + bb1), w1, p1);
                }
                p0 += __shfl_xor_sync(0xFFFFFFFFu, p0, 1);
                p0 += __shfl_xor_sync(0xFFFFFFFFu, p0, 2);
                p1 += __shfl_xor_sync(0xFFFFFFFFu, p1, 1);
                p1 += __shfl_xor_sync(0xFFFFFFFFu, p1, 2);
                if (tig == 0) {
                    const int row = mh * 64 + mt * 16 + gid;
                    part[nq * 128 + row]     = p0;
                    part[nq * 128 + row + 8] = p1;
                }
            }
        }
        __syncthreads();

        // ---- recon + squared error ----
        if (tid < 128) {
            const int p = tid;
            float recon = b4v + part[p] + part[128 + p]
                        + part[256 + p] + part[384 + p];
            float img = images[(size_t)(((b << 8) + r) << 8) + c0 + p];
            float e = img - recon;
            lacc = fmaf(e, e, lacc);
        }
    }

    // ---- block reduction ----
    __syncthreads();
    float* red = (float*)(smem + SM_RED);
    red[tid] = lacc;
    __syncthreads();
    #pragma unroll
    for (int s = 128; s > 0; s >>= 1) {
        if (tid < s) red[tid] += red[tid + s];
        __syncthreads();
    }
    if (tid == 0) g_partial[blockIdx.x] = red[0];
}

__global__ void reduce_kernel(float* __restrict__ out)
{
    __shared__ float s[256];
    float a = 0.0f;
    for (int i = threadIdx.x; i < NBLK; i += 256) a += g_partial[i];
    s[threadIdx.x] = a;
    __syncthreads();
    #pragma unroll
    for (int st = 128; st > 0; st >>= 1) {
        if (threadIdx.x < st) s[threadIdx.x] += s[threadIdx.x + st];
        __syncthreads();
    }
    if (threadIdx.x == 0)
        out[0] = s[0] * (1.0f / (float)(BB * 256 * 256));
}

extern "C" void kernel_launch(void* const* d_in, const int* in_sizes, int n_in,
                              void* d_out, int out_size)
{
    const float* images = (const float*)d_in[0];
    const float* W1     = (const float*)d_in[1];
    const float* b1     = (const float*)d_in[2];
    const float* W2     = (const float*)d_in[3];
    const float* b2     = (const float*)d_in[4];
    const float* W3     = (const float*)d_in[5];
    const float* b3     = (const float*)d_in[6];
    const float* W4     = (const float*)d_in[7];
    const float* b4     = (const float*)d_in[8];
    const int*   nptr   = (n_in > 10) ? (const int*)d_in[10] : nullptr;

    cudaFuncSetAttribute(mlp_mma_kernel,
                         cudaFuncAttributeMaxDynamicSharedMemorySize, SM_TOTAL);

    mlp_mma_kernel<<<NBLK, 256, SM_TOTAL>>>(images, W1, b1, W2, b2,
                                            W3, b3, W4, b4, nptr);
    reduce_kernel<<<1, 256>>>((float*)d_out);
}